// round 15
// baseline (speedup 1.0000x reference)
#include <cuda_runtime.h>
#include <cuda_fp16.h>
#include <cstdint>

#define NNODES 100000
#define NEDGES 1600000
#define NB1 ((NNODES + 255) / 256)

// ---------------- scratch (device globals; never passed from host) ---------
__device__ int   g_is64;
__device__ float g_deg[NNODES];
__device__ float g_dis[NNODES];
__device__ int   g_hist[NNODES];
__device__ int   g_row[NNODES + 1];
__device__ int   g_cursor[NNODES];
__device__ int   g_bsums[NB1];
__device__ int2  g_edge[NEDGES];
__device__ __half g_h1h[(size_t)NNODES * 128];   // layer-1 GEMM out (fp16)
__device__ __half g_a1h[(size_t)NNODES * 128];   // relu(agg1) = layer-2 input (fp16)
__device__ __half g_h2h[(size_t)NNODES * 64];    // layer-2 GEMM out (fp16)
// fp16 W images: n-major, k-stride 136 halves (272 B)
__device__ __half g_w1img[128 * 136];
__device__ __half g_w2img[64 * 136];

// ---------------- mma helpers (portable PTX, no 'a' features) ----------------
__device__ __forceinline__ uint32_t smem_u32(const void* p) {
    uint32_t a;
    asm("{ .reg .u64 t; cvta.to.shared.u64 t, %1; cvt.u32.u64 %0, t; }" : "=r"(a) : "l"(p));
    return a;
}
#define LDSM_X4(r, addr) \
    asm volatile("ldmatrix.sync.aligned.m8n8.x4.shared.b16 {%0,%1,%2,%3}, [%4];" \
        : "=r"((r)[0]), "=r"((r)[1]), "=r"((r)[2]), "=r"((r)[3]) : "r"(addr))
#define MMA_F16(c, a, b0, b1) \
    asm volatile("mma.sync.aligned.m16n8k16.row.col.f32.f16.f16.f32 " \
        "{%0,%1,%2,%3}, {%4,%5,%6,%7}, {%8,%9}, {%0,%1,%2,%3};" \
        : "+f"((c)[0]), "+f"((c)[1]), "+f"((c)[2]), "+f"((c)[3]) \
        : "r"((a)[0]), "r"((a)[1]), "r"((a)[2]), "r"((a)[3]), \
          "r"(b0), "r"(b1))

__device__ __forceinline__ uint32_t pack_f16x2(float f0, float f1) {
    uint32_t r;
    asm("cvt.rn.f16x2.f32 %0, %1, %2;" : "=r"(r) : "f"(f1), "f"(f0));
    return r;   // low half = f16(f0), high half = f16(f1)
}

// ---------------- W convert/transpose into fp16 image ----------------
__global__ void k_wconv(const float* __restrict__ W1, const float* __restrict__ W2) {
    int t = blockIdx.x * 256 + threadIdx.x;
    if (t < 128 * 128) {                     // W1[k][n]
        int k = t >> 7, n = t & 127;
        g_w1img[n * 136 + k] = __float2half(W1[t]);
    } else if (t < 128 * 128 + 128 * 64) {   // W2[k][n]
        int u = t - 128 * 128;
        int k = u >> 6, n = u & 63;
        g_w2img[n * 136 + k] = __float2half(W2[u]);
    }
}

// ---------------- init (+ fused edge_index dtype detection) ----------------
__global__ void k_init(const int* __restrict__ ei_raw) {
    int i = blockIdx.x * 256 + threadIdx.x;
    if (i < NNODES) { g_deg[i] = 1.0f; g_hist[i] = 0; }
    if (blockIdx.x == 0) {
        int bad = 0;
        for (int k = threadIdx.x; k < 2048; k += 256)
            bad |= (ei_raw[2 * k + 1] != 0);
        bad = __syncthreads_or(bad);
        if (threadIdx.x == 0) g_is64 = !bad;
    }
}

__device__ __forceinline__ void load_edge(const void* __restrict__ ei, int e,
                                          int& s, int& d) {
    if (g_is64) {
        const long long* p = (const long long*)ei;
        s = (int)p[e]; d = (int)p[NEDGES + e];
    } else {
        const int* p = (const int*)ei;
        s = p[e]; d = p[NEDGES + e];
    }
}

__global__ void k_deg(const void* __restrict__ ei, const float* __restrict__ ew) {
    int e = blockIdx.x * 256 + threadIdx.x;
    if (e < NEDGES) {
        int s, d; load_edge(ei, e, s, d);
        atomicAdd(&g_deg[d], ew[e]);
        atomicAdd(&g_hist[d], 1);
    }
}

__global__ void k_scan1() {
    __shared__ int sh[256];
    int i = blockIdx.x * 256 + threadIdx.x;
    int tid = threadIdx.x;
    if (i < NNODES) g_dis[i] = rsqrtf(g_deg[i]);
    int v = (i < NNODES) ? g_hist[i] : 0;
    sh[tid] = v; __syncthreads();
    for (int off = 1; off < 256; off <<= 1) {
        int t = (tid >= off) ? sh[tid - off] : 0;
        __syncthreads(); sh[tid] += t; __syncthreads();
    }
    if (i < NNODES) g_row[i] = sh[tid] - v;
    if (tid == 255) g_bsums[blockIdx.x] = sh[tid];
}

__global__ void k_scan2() {
    __shared__ int sh[512];
    int tid = threadIdx.x;
    int v = (tid < NB1) ? g_bsums[tid] : 0;
    sh[tid] = v; __syncthreads();
    for (int off = 1; off < 512; off <<= 1) {
        int t = (tid >= off) ? sh[tid - off] : 0;
        __syncthreads(); sh[tid] += t; __syncthreads();
    }
    if (tid < NB1) g_bsums[tid] = sh[tid] - v;
}

__global__ void k_scan3() {
    int i = blockIdx.x * 256 + threadIdx.x;
    if (i < NNODES) {
        int r = g_row[i] + g_bsums[blockIdx.x];
        g_row[i] = r;
        g_cursor[i] = r;
        if (i == 0) g_row[NNODES] = NEDGES;
    }
}

__global__ void k_sort(const void* __restrict__ ei, const float* __restrict__ ew) {
    int e = blockIdx.x * 256 + threadIdx.x;
    if (e < NEDGES) {
        int s, d; load_edge(ei, e, s, d);
        float nrm = g_dis[s] * ew[e] * g_dis[d];
        int pos = atomicAdd(&g_cursor[d], 1);
        g_edge[pos] = make_int2(s, __float_as_int(nrm));
    }
}

// ---------------- tensor-core GEMM (fp16 1-pass): H = X @ W ----------------
template<int NCOL, int LAYER>
__global__ __launch_bounds__(256, 2) void gemm_mma(
    const float* __restrict__ Xin, int M)
{
    constexpr int STR = 272;                 // bytes per fp16 row (136 halves)
    constexpr int XT  = 128 * STR;           // 34816 B X tile
    constexpr int WT  = NCOL * STR;          // W tile bytes
    constexpr int NF  = NCOL / 8;            // n-frags per warp (16 or 8)

    extern __shared__ __align__(16) char smem[];
    char* xs = smem;
    char* ws = xs + XT;

    __half* __restrict__ H = (LAYER == 1) ? g_h1h : g_h2h;

    const int tid  = threadIdx.x;
    const int lane = tid & 31;
    const int wid  = tid >> 5;
    const int row0 = blockIdx.x * 128;
    const int valid = M - row0;

    if (LAYER == 1) {
        for (int u = tid; u < 128 * 32; u += 256) {
            int r = u >> 5, c4 = u & 31;
            float4 v = make_float4(0.f, 0.f, 0.f, 0.f);
            if (r < valid)
                v = reinterpret_cast<const float4*>(Xin)[(size_t)(row0 + r) * 32 + c4];
            uint2 p;
            p.x = pack_f16x2(v.x, v.y);
            p.y = pack_f16x2(v.z, v.w);
            *reinterpret_cast<uint2*>(xs + r * STR + c4 * 8) = p;
        }
    } else {
        const uint4* A = reinterpret_cast<const uint4*>(g_a1h);
        for (int u = tid; u < 128 * 16; u += 256) {
            int r = u >> 4, c = u & 15;
            uint4 v = make_uint4(0u, 0u, 0u, 0u);
            if (r < valid)
                v = A[(size_t)(row0 + r) * 16 + c];
            *reinterpret_cast<uint4*>(xs + r * STR + c * 16) = v;
        }
    }
    {
        const uint4* wsrc = (LAYER == 1)
            ? reinterpret_cast<const uint4*>(g_w1img)
            : reinterpret_cast<const uint4*>(g_w2img);
        uint4* wdst = reinterpret_cast<uint4*>(ws);
        for (int u = tid; u < WT / 16; u += 256)
            wdst[u] = wsrc[u];
    }
    __syncthreads();

    const int mb = wid * 16;
    int a_row = mb + (lane & 7) + ((lane >> 3) & 1) * 8;
    uint32_t ah_base = smem_u32(xs) + a_row * STR + ((lane >> 4) & 1) * 16;
    uint32_t b_base = smem_u32(ws)
                    + (((lane >> 4) & 1) * 8 + (lane & 7)) * STR
                    + ((lane >> 3) & 1) * 16;

    float c[NF][4];
#pragma unroll
    for (int nf = 0; nf < NF; nf++)
#pragma unroll
        for (int q = 0; q < 4; q++) c[nf][q] = 0.f;

#pragma unroll
    for (int ks = 0; ks < 8; ks++) {
        uint32_t a[4];
        LDSM_X4(a, ah_base + ks * 32);
#pragma unroll
        for (int np = 0; np < NF / 2; np++) {
            uint32_t b[4];
            LDSM_X4(b, b_base + np * 16 * STR + ks * 32);
            MMA_F16(c[2 * np],     a, b[0], b[1]);
            MMA_F16(c[2 * np + 1], a, b[2], b[3]);
        }
    }

    uint32_t* Hu = reinterpret_cast<uint32_t*>(H);
    int r0 = row0 + mb + (lane >> 2);
    int cq = lane & 3;
#pragma unroll
    for (int nf = 0; nf < NF; nf++) {
        if (r0 < M)
            Hu[(size_t)r0 * (NCOL / 2) + nf * 4 + cq] = pack_f16x2(c[nf][0], c[nf][1]);
        if (r0 + 8 < M)
            Hu[(size_t)(r0 + 8) * (NCOL / 2) + nf * 4 + cq] = pack_f16x2(c[nf][2], c[nf][3]);
    }
}

// ---------------- segmented aggregation: one warp per dst node --------------
// 4-wide edge unroll: 4 independent gather chains in flight (MLP=4).
__global__ __launch_bounds__(256) void agg1(const float* __restrict__ bias) {
    int w = (blockIdx.x * 256 + threadIdx.x) >> 5;
    int lane = threadIdx.x & 31;
    if (w >= NNODES) return;
    const uint2* H = reinterpret_cast<const uint2*>(g_h1h);
    const int2* E = g_edge;

    int beg = g_row[w], end = g_row[w + 1];
    float ds = g_dis[w];
    float s2 = ds * ds;

    uint2 hv = H[(size_t)w * 32 + lane];
    float2 f0 = __half22float2(*reinterpret_cast<__half2*>(&hv.x));
    float2 f1 = __half22float2(*reinterpret_cast<__half2*>(&hv.y));
    float p0 = s2 * f0.x, p1 = s2 * f0.y, p2 = s2 * f1.x, p3 = s2 * f1.y;
    float q0 = 0.f, q1 = 0.f, q2 = 0.f, q3 = 0.f;
    float r0 = 0.f, r1 = 0.f, r2 = 0.f, r3 = 0.f;
    float t0 = 0.f, t1 = 0.f, t2 = 0.f, t3 = 0.f;

    int e = beg;
    for (; e + 3 < end; e += 4) {
        int2 m0 = E[e], m1 = E[e + 1], m2 = E[e + 2], m3 = E[e + 3];
        uint2 v0 = H[(size_t)m0.x * 32 + lane];
        uint2 v1 = H[(size_t)m1.x * 32 + lane];
        uint2 v2 = H[(size_t)m2.x * 32 + lane];
        uint2 v3 = H[(size_t)m3.x * 32 + lane];
        float n0 = __int_as_float(m0.y), n1 = __int_as_float(m1.y);
        float n2 = __int_as_float(m2.y), n3 = __int_as_float(m3.y);
        float2 g0, g1;
        g0 = __half22float2(*reinterpret_cast<__half2*>(&v0.x));
        g1 = __half22float2(*reinterpret_cast<__half2*>(&v0.y));
        p0 = fmaf(n0, g0.x, p0); p1 = fmaf(n0, g0.y, p1);
        p2 = fmaf(n0, g1.x, p2); p3 = fmaf(n0, g1.y, p3);
        g0 = __half22float2(*reinterpret_cast<__half2*>(&v1.x));
        g1 = __half22float2(*reinterpret_cast<__half2*>(&v1.y));
        q0 = fmaf(n1, g0.x, q0); q1 = fmaf(n1, g0.y, q1);
        q2 = fmaf(n1, g1.x, q2); q3 = fmaf(n1, g1.y, q3);
        g0 = __half22float2(*reinterpret_cast<__half2*>(&v2.x));
        g1 = __half22float2(*reinterpret_cast<__half2*>(&v2.y));
        r0 = fmaf(n2, g0.x, r0); r1 = fmaf(n2, g0.y, r1);
        r2 = fmaf(n2, g1.x, r2); r3 = fmaf(n2, g1.y, r3);
        g0 = __half22float2(*reinterpret_cast<__half2*>(&v3.x));
        g1 = __half22float2(*reinterpret_cast<__half2*>(&v3.y));
        t0 = fmaf(n3, g0.x, t0); t1 = fmaf(n3, g0.y, t1);
        t2 = fmaf(n3, g1.x, t2); t3 = fmaf(n3, g1.y, t3);
    }
    for (; e < end; e++) {
        int2 md = E[e];
        float nm = __int_as_float(md.y);
        uint2 v = H[(size_t)md.x * 32 + lane];
        float2 g0 = __half22float2(*reinterpret_cast<__half2*>(&v.x));
        float2 g1 = __half22float2(*reinterpret_cast<__half2*>(&v.y));
        p0 = fmaf(nm, g0.x, p0); p1 = fmaf(nm, g0.y, p1);
        p2 = fmaf(nm, g1.x, p2); p3 = fmaf(nm, g1.y, p3);
    }
    float a0 = (p0 + q0) + (r0 + t0);
    float a1 = (p1 + q1) + (r1 + t1);
    float a2 = (p2 + q2) + (r2 + t2);
    float a3 = (p3 + q3) + (r3 + t3);

    float4 bv = reinterpret_cast<const float4*>(bias)[lane];
    a0 = fmaxf(a0 + bv.x, 0.f);
    a1 = fmaxf(a1 + bv.y, 0.f);
    a2 = fmaxf(a2 + bv.z, 0.f);
    a3 = fmaxf(a3 + bv.w, 0.f);
    uint2 o;
    o.x = pack_f16x2(a0, a1);
    o.y = pack_f16x2(a2, a3);
    reinterpret_cast<uint2*>(g_a1h)[(size_t)w * 32 + lane] = o;
}

__global__ __launch_bounds__(256) void agg2(const float* __restrict__ bias,
                                            float* __restrict__ out) {
    int w = (blockIdx.x * 256 + threadIdx.x) >> 5;
    int lane = threadIdx.x & 31;
    if (w >= NNODES) return;
    const uint32_t* H = reinterpret_cast<const uint32_t*>(g_h2h);
    const int2* E = g_edge;

    int beg = g_row[w], end = g_row[w + 1];
    float ds = g_dis[w];
    float s2 = ds * ds;

    uint32_t hv = H[(size_t)w * 32 + lane];
    float2 f = __half22float2(*reinterpret_cast<__half2*>(&hv));
    float p0 = s2 * f.x, p1 = s2 * f.y;
    float q0 = 0.f, q1 = 0.f, r0 = 0.f, r1 = 0.f, t0 = 0.f, t1 = 0.f;

    int e = beg;
    for (; e + 3 < end; e += 4) {
        int2 m0 = E[e], m1 = E[e + 1], m2 = E[e + 2], m3 = E[e + 3];
        uint32_t v0 = H[(size_t)m0.x * 32 + lane];
        uint32_t v1 = H[(size_t)m1.x * 32 + lane];
        uint32_t v2 = H[(size_t)m2.x * 32 + lane];
        uint32_t v3 = H[(size_t)m3.x * 32 + lane];
        float2 g;
        g = __half22float2(*reinterpret_cast<__half2*>(&v0));
        p0 = fmaf(__int_as_float(m0.y), g.x, p0);
        p1 = fmaf(__int_as_float(m0.y), g.y, p1);
        g = __half22float2(*reinterpret_cast<__half2*>(&v1));
        q0 = fmaf(__int_as_float(m1.y), g.x, q0);
        q1 = fmaf(__int_as_float(m1.y), g.y, q1);
        g = __half22float2(*reinterpret_cast<__half2*>(&v2));
        r0 = fmaf(__int_as_float(m2.y), g.x, r0);
        r1 = fmaf(__int_as_float(m2.y), g.y, r1);
        g = __half22float2(*reinterpret_cast<__half2*>(&v3));
        t0 = fmaf(__int_as_float(m3.y), g.x, t0);
        t1 = fmaf(__int_as_float(m3.y), g.y, t1);
    }
    for (; e < end; e++) {
        int2 md = E[e];
        float nm = __int_as_float(md.y);
        uint32_t v = H[(size_t)md.x * 32 + lane];
        float2 g = __half22float2(*reinterpret_cast<__half2*>(&v));
        p0 = fmaf(nm, g.x, p0);
        p1 = fmaf(nm, g.y, p1);
    }
    float a0 = (p0 + q0) + (r0 + t0);
    float a1 = (p1 + q1) + (r1 + t1);

    float2 bv = reinterpret_cast<const float2*>(bias)[lane];
    float2 o = make_float2(a0 + bv.x, a1 + bv.y);
    reinterpret_cast<float2*>(out)[(size_t)w * 32 + lane] = o;
}

// ---------------- launch (two-stream fork/join, graph-capturable) ----------
extern "C" void kernel_launch(void* const* d_in, const int* in_sizes, int n_in,
                              void* d_out, int out_size)
{
    const float* x  = (const float*)d_in[0];
    const void*  ei = d_in[1];
    const float* ew = (const float*)d_in[2];
    const float* W1 = (const float*)d_in[3];
    const float* b1 = (const float*)d_in[4];
    const float* W2 = (const float*)d_in[5];
    const float* b2 = (const float*)d_in[6];
    float* out = (float*)d_out;

    const int nb_nodes = (NNODES + 255) / 256;
    const int nb_edges = (NEDGES + 255) / 256;
    const int nb_rows  = (NNODES + 127) / 128;   // 782
    const int nb_warps = (NNODES * 32 + 255) / 256;

    constexpr int SM1 = 128 * 272 + 128 * 272;   // 69632 B
    constexpr int SM2 = 128 * 272 + 64 * 272;    // 52224 B

    static cudaStream_t s1 = nullptr;
    static cudaEvent_t evFork = nullptr, evJoin = nullptr;
    if (!s1) {
        cudaFuncSetAttribute(gemm_mma<128, 1>,
                             cudaFuncAttributeMaxDynamicSharedMemorySize, SM1);
        cudaFuncSetAttribute(gemm_mma<64, 2>,
                             cudaFuncAttributeMaxDynamicSharedMemorySize, SM2);
        cudaStreamCreateWithFlags(&s1, cudaStreamNonBlocking);
        cudaEventCreateWithFlags(&evFork, cudaEventDisableTiming);
        cudaEventCreateWithFlags(&evJoin, cudaEventDisableTiming);
    }

    // fork: branch B (CSR build) on s1, branch A (wconv+gemm1) on capture stream
    cudaEventRecord(evFork, 0);
    cudaStreamWaitEvent(s1, evFork, 0);

    k_init<<<nb_nodes, 256, 0, s1>>>((const int*)ei);            // 0
    k_deg<<<nb_edges, 256, 0, s1>>>(ei, ew);                     // 1
    k_wconv<<<96, 256>>>(W1, W2);                                // 2
    gemm_mma<128, 1><<<nb_rows, 256, SM1>>>(x, NNODES);          // 3 <- profiled
    k_scan1<<<nb_nodes, 256, 0, s1>>>();                         // 4
    k_scan2<<<1, 512, 0, s1>>>();                                // 5
    k_scan3<<<nb_nodes, 256, 0, s1>>>();                         // 6
    k_sort<<<nb_edges, 256, 0, s1>>>(ei, ew);                    // 7

    // join: serial tail needs both branches
    cudaEventRecord(evJoin, s1);
    cudaStreamWaitEvent(0, evJoin, 0);

    agg1<<<nb_warps, 256>>>(b1);                                 // 8
    gemm_mma<64, 2><<<nb_rows, 256, SM2>>>(nullptr, NNODES);     // 9
    agg2<<<nb_warps, 256>>>(b2, out);                            // 10
}

// round 16
// speedup vs baseline: 1.1399x; 1.1399x over previous
#include <cuda_runtime.h>
#include <cuda_fp16.h>
#include <cstdint>

#define NNODES 100000
#define NEDGES 1600000
#define NB1 ((NNODES + 255) / 256)

// ---------------- scratch (device globals; never passed from host) ---------
__device__ int   g_is64;
__device__ float g_deg[NNODES];
__device__ float g_dis[NNODES];
__device__ int   g_hist[NNODES];
__device__ int   g_row[NNODES + 1];
__device__ int   g_cursor[NNODES];
__device__ int   g_bsums[NB1];
__device__ int2  g_edge[NEDGES];
__device__ __half g_h1h[(size_t)NNODES * 128];   // layer-1 GEMM out (fp16)
__device__ __half g_a1h[(size_t)NNODES * 128];   // relu(agg1) = layer-2 input (fp16)
__device__ __half g_h2h[(size_t)NNODES * 64];    // layer-2 GEMM out (fp16)
// fp16 W images: n-major, k-stride 136 halves (272 B)
__device__ __half g_w1img[128 * 136];
__device__ __half g_w2img[64 * 136];

// ---------------- mma / async-copy helpers (portable PTX) ----------------
__device__ __forceinline__ uint32_t smem_u32(const void* p) {
    uint32_t a;
    asm("{ .reg .u64 t; cvta.to.shared.u64 t, %1; cvt.u32.u64 %0, t; }" : "=r"(a) : "l"(p));
    return a;
}
__device__ __forceinline__ void cp16(uint32_t dst, const void* src) {
    asm volatile("cp.async.cg.shared.global [%0], [%1], 16;" :: "r"(dst), "l"(src));
}
__device__ __forceinline__ void cp_wait_all() {
    asm volatile("cp.async.commit_group;");
    asm volatile("cp.async.wait_group 0;");
}
#define LDSM_X4(r, addr) \
    asm volatile("ldmatrix.sync.aligned.m8n8.x4.shared.b16 {%0,%1,%2,%3}, [%4];" \
        : "=r"((r)[0]), "=r"((r)[1]), "=r"((r)[2]), "=r"((r)[3]) : "r"(addr))
#define MMA_F16(c, a, b0, b1) \
    asm volatile("mma.sync.aligned.m16n8k16.row.col.f32.f16.f16.f32 " \
        "{%0,%1,%2,%3}, {%4,%5,%6,%7}, {%8,%9}, {%0,%1,%2,%3};" \
        : "+f"((c)[0]), "+f"((c)[1]), "+f"((c)[2]), "+f"((c)[3]) \
        : "r"((a)[0]), "r"((a)[1]), "r"((a)[2]), "r"((a)[3]), \
          "r"(b0), "r"(b1))

__device__ __forceinline__ uint32_t pack_f16x2(float f0, float f1) {
    uint32_t r;
    asm("cvt.rn.f16x2.f32 %0, %1, %2;" : "=r"(r) : "f"(f1), "f"(f0));
    return r;   // low half = f16(f0), high half = f16(f1)
}

// ---------------- W convert/transpose into fp16 image ----------------
__global__ void k_wconv(const float* __restrict__ W1, const float* __restrict__ W2) {
    int t = blockIdx.x * 256 + threadIdx.x;
    if (t < 128 * 128) {                     // W1[k][n]
        int k = t >> 7, n = t & 127;
        g_w1img[n * 136 + k] = __float2half(W1[t]);
    } else if (t < 128 * 128 + 128 * 64) {   // W2[k][n]
        int u = t - 128 * 128;
        int k = u >> 6, n = u & 63;
        g_w2img[n * 136 + k] = __float2half(W2[u]);
    }
}

// ---------------- init (+ fused edge_index dtype detection) ----------------
__global__ void k_init(const int* __restrict__ ei_raw) {
    int i = blockIdx.x * 256 + threadIdx.x;
    if (i < NNODES) { g_deg[i] = 1.0f; g_hist[i] = 0; }
    if (blockIdx.x == 0) {
        int bad = 0;
        for (int k = threadIdx.x; k < 2048; k += 256)
            bad |= (ei_raw[2 * k + 1] != 0);
        bad = __syncthreads_or(bad);
        if (threadIdx.x == 0) g_is64 = !bad;
    }
}

__device__ __forceinline__ void load_edge(const void* __restrict__ ei, int e,
                                          int& s, int& d) {
    if (g_is64) {
        const long long* p = (const long long*)ei;
        s = (int)p[e]; d = (int)p[NEDGES + e];
    } else {
        const int* p = (const int*)ei;
        s = p[e]; d = p[NEDGES + e];
    }
}

__global__ void k_deg(const void* __restrict__ ei, const float* __restrict__ ew) {
    int e = blockIdx.x * 256 + threadIdx.x;
    if (e < NEDGES) {
        int s, d; load_edge(ei, e, s, d);
        atomicAdd(&g_deg[d], ew[e]);
        atomicAdd(&g_hist[d], 1);
    }
}

__global__ void k_scan1() {
    __shared__ int sh[256];
    int i = blockIdx.x * 256 + threadIdx.x;
    int tid = threadIdx.x;
    if (i < NNODES) g_dis[i] = rsqrtf(g_deg[i]);
    int v = (i < NNODES) ? g_hist[i] : 0;
    sh[tid] = v; __syncthreads();
    for (int off = 1; off < 256; off <<= 1) {
        int t = (tid >= off) ? sh[tid - off] : 0;
        __syncthreads(); sh[tid] += t; __syncthreads();
    }
    if (i < NNODES) g_row[i] = sh[tid] - v;
    if (tid == 255) g_bsums[blockIdx.x] = sh[tid];
}

__global__ void k_scan2() {
    __shared__ int sh[512];
    int tid = threadIdx.x;
    int v = (tid < NB1) ? g_bsums[tid] : 0;
    sh[tid] = v; __syncthreads();
    for (int off = 1; off < 512; off <<= 1) {
        int t = (tid >= off) ? sh[tid - off] : 0;
        __syncthreads(); sh[tid] += t; __syncthreads();
    }
    if (tid < NB1) g_bsums[tid] = sh[tid] - v;
}

__global__ void k_scan3() {
    int i = blockIdx.x * 256 + threadIdx.x;
    if (i < NNODES) {
        int r = g_row[i] + g_bsums[blockIdx.x];
        g_row[i] = r;
        g_cursor[i] = r;
        if (i == 0) g_row[NNODES] = NEDGES;
    }
}

__global__ void k_sort(const void* __restrict__ ei, const float* __restrict__ ew) {
    int e = blockIdx.x * 256 + threadIdx.x;
    if (e < NEDGES) {
        int s, d; load_edge(ei, e, s, d);
        float nrm = g_dis[s] * ew[e] * g_dis[d];
        int pos = atomicAdd(&g_cursor[d], 1);
        g_edge[pos] = make_int2(s, __float_as_int(nrm));
    }
}

// ---------------- tensor-core GEMM (fp16 1-pass): H = X @ W ----------------
// W tile (both layers) and X tile (layer 2) staged via cp.async.cg.
template<int NCOL, int LAYER>
__global__ __launch_bounds__(256, 2) void gemm_mma(
    const float* __restrict__ Xin, int M)
{
    constexpr int STR = 272;                 // bytes per fp16 row (136 halves)
    constexpr int XT  = 128 * STR;           // 34816 B X tile
    constexpr int WT  = NCOL * STR;          // W tile bytes
    constexpr int NF  = NCOL / 8;            // n-frags per warp (16 or 8)

    extern __shared__ __align__(16) char smem[];
    char* xs = smem;
    char* ws = xs + XT;

    __half* __restrict__ H = (LAYER == 1) ? g_h1h : g_h2h;

    const int tid  = threadIdx.x;
    const int lane = tid & 31;
    const int wid  = tid >> 5;
    const int row0 = blockIdx.x * 128;
    const int valid = M - row0;
    const uint32_t xs_u = smem_u32(xs);
    const uint32_t ws_u = smem_u32(ws);

    // stage W via cp.async (image is the exact smem layout)
    {
        const char* wsrc = (LAYER == 1) ? (const char*)g_w1img : (const char*)g_w2img;
        for (int u = tid; u < WT / 16; u += 256)
            cp16(ws_u + u * 16, wsrc + u * 16);
    }
    if (LAYER == 1) {
        // stage X: fp32 -> fp16 cvt path (cannot convert in cp.async)
        for (int u = tid; u < 128 * 32; u += 256) {
            int r = u >> 5, c4 = u & 31;
            float4 v = make_float4(0.f, 0.f, 0.f, 0.f);
            if (r < valid)
                v = reinterpret_cast<const float4*>(Xin)[(size_t)(row0 + r) * 32 + c4];
            uint2 p;
            p.x = pack_f16x2(v.x, v.y);
            p.y = pack_f16x2(v.z, v.w);
            *reinterpret_cast<uint2*>(xs + r * STR + c4 * 8) = p;
        }
    } else {
        // stage X: already fp16 in g_a1h — cp.async rows, zero-fill the rest
        const char* A = (const char*)g_a1h;
        for (int u = tid; u < 128 * 16; u += 256) {
            int r = u >> 4, c = u & 15;
            if (r < valid)
                cp16(xs_u + r * STR + c * 16, A + ((size_t)(row0 + r) * 16 + c) * 16);
            else
                *reinterpret_cast<uint4*>(xs + r * STR + c * 16) =
                    make_uint4(0u, 0u, 0u, 0u);
        }
    }
    cp_wait_all();
    __syncthreads();

    const int mb = wid * 16;
    int a_row = mb + (lane & 7) + ((lane >> 3) & 1) * 8;
    uint32_t ah_base = xs_u + a_row * STR + ((lane >> 4) & 1) * 16;
    uint32_t b_base = ws_u
                    + (((lane >> 4) & 1) * 8 + (lane & 7)) * STR
                    + ((lane >> 3) & 1) * 16;

    float c[NF][4];
#pragma unroll
    for (int nf = 0; nf < NF; nf++)
#pragma unroll
        for (int q = 0; q < 4; q++) c[nf][q] = 0.f;

#pragma unroll
    for (int ks = 0; ks < 8; ks++) {
        uint32_t a[4];
        LDSM_X4(a, ah_base + ks * 32);
#pragma unroll
        for (int np = 0; np < NF / 2; np++) {
            uint32_t b[4];
            LDSM_X4(b, b_base + np * 16 * STR + ks * 32);
            MMA_F16(c[2 * np],     a, b[0], b[1]);
            MMA_F16(c[2 * np + 1], a, b[2], b[3]);
        }
    }

    uint32_t* Hu = reinterpret_cast<uint32_t*>(H);
    int r0 = row0 + mb + (lane >> 2);
    int cq = lane & 3;
#pragma unroll
    for (int nf = 0; nf < NF; nf++) {
        if (r0 < M)
            Hu[(size_t)r0 * (NCOL / 2) + nf * 4 + cq] = pack_f16x2(c[nf][0], c[nf][1]);
        if (r0 + 8 < M)
            Hu[(size_t)(r0 + 8) * (NCOL / 2) + nf * 4 + cq] = pack_f16x2(c[nf][2], c[nf][3]);
    }
}

// ---------------- segmented aggregation (exact R13 form) -------------------
__global__ __launch_bounds__(256) void agg1(const float* __restrict__ bias) {
    int w = (blockIdx.x * 256 + threadIdx.x) >> 5;
    int lane = threadIdx.x & 31;
    if (w >= NNODES) return;
    const uint2* H = reinterpret_cast<const uint2*>(g_h1h);

    int beg = g_row[w], end = g_row[w + 1];
    float ds = g_dis[w];
    float s2 = ds * ds;

    uint2 hv = H[(size_t)w * 32 + lane];
    float2 f0 = __half22float2(*reinterpret_cast<__half2*>(&hv.x));
    float2 f1 = __half22float2(*reinterpret_cast<__half2*>(&hv.y));
    float a0 = s2 * f0.x, a1 = s2 * f0.y, a2 = s2 * f1.x, a3 = s2 * f1.y;

    for (int e = beg; e < end; e++) {
        int2 md = g_edge[e];
        float nm = __int_as_float(md.y);
        uint2 v = H[(size_t)md.x * 32 + lane];
        float2 g0 = __half22float2(*reinterpret_cast<__half2*>(&v.x));
        float2 g1 = __half22float2(*reinterpret_cast<__half2*>(&v.y));
        a0 = fmaf(nm, g0.x, a0);
        a1 = fmaf(nm, g0.y, a1);
        a2 = fmaf(nm, g1.x, a2);
        a3 = fmaf(nm, g1.y, a3);
    }
    float4 bv = reinterpret_cast<const float4*>(bias)[lane];
    a0 = fmaxf(a0 + bv.x, 0.f);
    a1 = fmaxf(a1 + bv.y, 0.f);
    a2 = fmaxf(a2 + bv.z, 0.f);
    a3 = fmaxf(a3 + bv.w, 0.f);
    uint2 o;
    o.x = pack_f16x2(a0, a1);
    o.y = pack_f16x2(a2, a3);
    reinterpret_cast<uint2*>(g_a1h)[(size_t)w * 32 + lane] = o;
}

__global__ __launch_bounds__(256) void agg2(const float* __restrict__ bias,
                                            float* __restrict__ out) {
    int w = (blockIdx.x * 256 + threadIdx.x) >> 5;
    int lane = threadIdx.x & 31;
    if (w >= NNODES) return;
    const uint32_t* H = reinterpret_cast<const uint32_t*>(g_h2h);

    int beg = g_row[w], end = g_row[w + 1];
    float ds = g_dis[w];
    float s2 = ds * ds;

    uint32_t hv = H[(size_t)w * 32 + lane];
    float2 f = __half22float2(*reinterpret_cast<__half2*>(&hv));
    float a0 = s2 * f.x, a1 = s2 * f.y;

    for (int e = beg; e < end; e++) {
        int2 md = g_edge[e];
        float nm = __int_as_float(md.y);
        uint32_t v = H[(size_t)md.x * 32 + lane];
        float2 g = __half22float2(*reinterpret_cast<__half2*>(&v));
        a0 = fmaf(nm, g.x, a0);
        a1 = fmaf(nm, g.y, a1);
    }
    float2 bv = reinterpret_cast<const float2*>(bias)[lane];
    float2 o = make_float2(a0 + bv.x, a1 + bv.y);
    reinterpret_cast<float2*>(out)[(size_t)w * 32 + lane] = o;
}

// ---------------- launch (two-stream fork/join, graph-capturable) ----------
extern "C" void kernel_launch(void* const* d_in, const int* in_sizes, int n_in,
                              void* d_out, int out_size)
{
    const float* x  = (const float*)d_in[0];
    const void*  ei = d_in[1];
    const float* ew = (const float*)d_in[2];
    const float* W1 = (const float*)d_in[3];
    const float* b1 = (const float*)d_in[4];
    const float* W2 = (const float*)d_in[5];
    const float* b2 = (const float*)d_in[6];
    float* out = (float*)d_out;

    const int nb_nodes = (NNODES + 255) / 256;
    const int nb_edges = (NEDGES + 255) / 256;
    const int nb_rows  = (NNODES + 127) / 128;   // 782
    const int nb_warps = (NNODES * 32 + 255) / 256;

    constexpr int SM1 = 128 * 272 + 128 * 272;   // 69632 B
    constexpr int SM2 = 128 * 272 + 64 * 272;    // 52224 B

    static cudaStream_t s1 = nullptr;
    static cudaEvent_t evFork = nullptr, evJoin = nullptr;
    if (!s1) {
        cudaFuncSetAttribute(gemm_mma<128, 1>,
                             cudaFuncAttributeMaxDynamicSharedMemorySize, SM1);
        cudaFuncSetAttribute(gemm_mma<64, 2>,
                             cudaFuncAttributeMaxDynamicSharedMemorySize, SM2);
        cudaStreamCreateWithFlags(&s1, cudaStreamNonBlocking);
        cudaEventCreateWithFlags(&evFork, cudaEventDisableTiming);
        cudaEventCreateWithFlags(&evJoin, cudaEventDisableTiming);
    }

    // fork: branch B (CSR build) on s1, branch A (wconv+gemm1) on capture stream
    cudaEventRecord(evFork, 0);
    cudaStreamWaitEvent(s1, evFork, 0);

    k_init<<<nb_nodes, 256, 0, s1>>>((const int*)ei);            // 0
    k_deg<<<nb_edges, 256, 0, s1>>>(ei, ew);                     // 1
    k_wconv<<<96, 256>>>(W1, W2);                                // 2
    gemm_mma<128, 1><<<nb_rows, 256, SM1>>>(x, NNODES);          // 3 <- profiled
    k_scan1<<<nb_nodes, 256, 0, s1>>>();                         // 4
    k_scan2<<<1, 512, 0, s1>>>();                                // 5
    k_scan3<<<nb_nodes, 256, 0, s1>>>();                         // 6
    k_sort<<<nb_edges, 256, 0, s1>>>(ei, ew);                    // 7

    // join: serial tail needs both branches
    cudaEventRecord(evJoin, s1);
    cudaStreamWaitEvent(0, evJoin, 0);

    agg1<<<nb_warps, 256>>>(b1);                                 // 8
    gemm_mma<64, 2><<<nb_rows, 256, SM2>>>(nullptr, NNODES);     // 9
    agg2<<<nb_warps, 256>>>(b2, out);                            // 10
}